// round 4
// baseline (speedup 1.0000x reference)
#include <cuda_runtime.h>
#include <cstdint>

// BilinearInteraction: out[b, p, :] = x[b, i_p, :] * (x[b, j_p, :] @ W)
//   x: [4096, 32, 64] f32, W: [64, 64] f32, out: [4096, 496, 64] f32
//   4 batches per CTA; lane-group-packed GEMM to kill broadcast LDS waste.

#define NF 32
#define ED 64
#define NP 496
#define NTHREADS 256
#define NBATCH 4096
#define BPC 4                    // batches per CTA

// Dynamic SMEM layout, in float4 units:
//   xs: 4 tiles, stride 514 f4 (2056 floats = 8224 B; 8224 % 128 == 32
//       -> tiles sit at distinct 32B quarter-phases, conflict-free packing)
//   Ws: 1024 f4 at offset 2056
//   vs: 4 tiles, stride 512 f4, at offset 3080
#define XS_STR4 514
#define WS_OFF4 (BPC * XS_STR4)          // 2056
#define VS_OFF4 (WS_OFF4 + 1024)         // 3080
#define VS_STR4 512
#define SMEM_F4 (VS_OFF4 + BPC * VS_STR4)   // 5128 f4 = 82048 B

__global__ void __launch_bounds__(NTHREADS, 2)
bilinear_kernel(const float* __restrict__ x,
                const float* __restrict__ W,
                float* __restrict__ out)
{
    extern __shared__ float4 sm4[];

    const int tid    = threadIdx.x;
    const int b_base = blockIdx.x * BPC;

    // ---- Prologue: load 4 batches of x (2048 f4) + W (1024 f4) ----
    {
        const float4* xg = (const float4*)(x + (size_t)b_base * (NF * ED));
#pragma unroll
        for (int k = 0; k < 8; k++) {
            const int idx = tid + k * NTHREADS;       // 0..2047
            const int t   = idx >> 9;                 // batch tile
            const int off = idx & 511;
            sm4[t * XS_STR4 + off] = xg[idx];
        }
        const float4* wg = (const float4*)W;
#pragma unroll
        for (int k = 0; k < 4; k++)
            sm4[WS_OFF4 + tid + k * NTHREADS] = wg[tid + k * NTHREADS];
    }
    __syncthreads();

    // ---- GEMM: vid[g][f][e] = sum_d x[g][f][d] * W[d][e] ----
    // lane group g = lane>>3 -> batch g; q = lane&7.
    // Thread owns rows f = w + 8r (r=0..3) and e-chunks {4q..4q+3} and {32+4q..+3}.
    // x LDS.128: 4 distinct f4 (one per tile quarter-phase) = 1 wf / 64B useful.
    // W LDS.128: 8 distinct f4 = 128B contiguous, dup across groups = 1 wf.
    {
        const int lane = tid & 31;
        const int w    = tid >> 5;
        const int g    = lane >> 3;
        const int q    = lane & 7;

        const float4* xt  = sm4 + g * XS_STR4;
        const float4* Ws4 = sm4 + WS_OFF4;

        float4 acc_a[4], acc_b[4];
#pragma unroll
        for (int r = 0; r < 4; r++) {
            acc_a[r] = make_float4(0.f, 0.f, 0.f, 0.f);
            acc_b[r] = make_float4(0.f, 0.f, 0.f, 0.f);
        }

#pragma unroll
        for (int d4 = 0; d4 < 16; d4++) {
            float4 xv[4];
#pragma unroll
            for (int r = 0; r < 4; r++)
                xv[r] = xt[(w + 8 * r) * 16 + d4];

#pragma unroll
            for (int dd = 0; dd < 4; dd++) {
                const int d = 4 * d4 + dd;
                const float4 w0 = Ws4[d * 16 + q];
                const float4 w1 = Ws4[d * 16 + 8 + q];
#pragma unroll
                for (int r = 0; r < 4; r++) {
                    const float xs = (dd == 0) ? xv[r].x :
                                     (dd == 1) ? xv[r].y :
                                     (dd == 2) ? xv[r].z : xv[r].w;
                    acc_a[r].x = fmaf(xs, w0.x, acc_a[r].x);
                    acc_a[r].y = fmaf(xs, w0.y, acc_a[r].y);
                    acc_a[r].z = fmaf(xs, w0.z, acc_a[r].z);
                    acc_a[r].w = fmaf(xs, w0.w, acc_a[r].w);
                    acc_b[r].x = fmaf(xs, w1.x, acc_b[r].x);
                    acc_b[r].y = fmaf(xs, w1.y, acc_b[r].y);
                    acc_b[r].z = fmaf(xs, w1.z, acc_b[r].z);
                    acc_b[r].w = fmaf(xs, w1.w, acc_b[r].w);
                }
            }
        }

        float4* vt = sm4 + VS_OFF4 + g * VS_STR4;
#pragma unroll
        for (int r = 0; r < 4; r++) {
            vt[(w + 8 * r) * 16 + q]     = acc_a[r];
            vt[(w + 8 * r) * 16 + 8 + q] = acc_b[r];
        }
    }
    __syncthreads();

    // ---- Write phase (R2 structure, per batch): row-sequential stores ----
    // Warp w owns rows {w, 30-w, 15-w, 15+w} (warp 0: {0, 30, 15}).
    {
        const int w    = tid >> 5;
        const int lane = tid & 31;
        const int v    = lane & 15;
        const int h    = lane >> 4;

        int rows[4];
        int nrows;
        if (w == 0) {
            rows[0] = 0; rows[1] = 30; rows[2] = 15; rows[3] = 0;
            nrows = 3;
        } else {
            rows[0] = w; rows[1] = 30 - w; rows[2] = 15 - w; rows[3] = 15 + w;
            nrows = 4;
        }

#pragma unroll
        for (int bt = 0; bt < BPC; bt++) {
            const float4* xs4  = sm4 + bt * XS_STR4;
            const float4* vs4  = sm4 + VS_OFF4 + bt * VS_STR4;
            float4*       out4 = (float4*)(out + (size_t)(b_base + bt) * (NP * ED));

#pragma unroll
            for (int r = 0; r < 4; r++) {
                if (r >= nrows) break;
                const int i = rows[r];
                const float4 a  = xs4[i * 16 + v];
                const int cnt   = 31 - i;
                const int iters = (cnt + 1) >> 1;
                const int p0    = (i * (63 - i)) >> 1;

#pragma unroll 2
                for (int t = 0; t < iters; t++) {
                    const int j = i + 1 + 2 * t + h;
                    if (j < NF) {
                        const float4 c = vs4[j * 16 + v];
                        const int p = p0 + (j - i - 1);
                        float4 rr;
                        rr.x = a.x * c.x;
                        rr.y = a.y * c.y;
                        rr.z = a.z * c.z;
                        rr.w = a.w * c.w;
                        out4[p * 16 + v] = rr;
                    }
                }
            }
        }
    }
}

extern "C" void kernel_launch(void* const* d_in, const int* in_sizes, int n_in,
                              void* d_out, int out_size)
{
    const float* x = (const float*)d_in[0];
    const float* W = (const float*)d_in[1];
    float*       o = (float*)d_out;

    static_assert(SMEM_F4 * 16 == 82048, "smem layout");
    cudaFuncSetAttribute(bilinear_kernel,
                         cudaFuncAttributeMaxDynamicSharedMemorySize,
                         SMEM_F4 * 16);
    bilinear_kernel<<<NBATCH / BPC, NTHREADS, SMEM_F4 * 16>>>(x, W, o);
}